// round 10
// baseline (speedup 1.0000x reference)
#include <cuda_runtime.h>
#include <cuda_bf16.h>
#include <stdint.h>
#include <math.h>
#include <float.h>

#define NTHREADS   256
#define T_REAL     200
#define MASK_VAL_F (-4294967296.0f)   // jnp.float32(-2**32+1) rounds to -2^32
#define MAXB       4096

// bf16 SMEM tiles, row stride 72 elements (144 B: 16B-aligned, conflict-free ldmatrix)
#define ROWB       144
#define WSTRIP     (16 * ROWB)             // 2304 B per-warp keys strip

// ---- SMEM byte offsets (main kernel) ----
#define OFF_KH    0                        // keys hi, 8 warp-strips : 18432
#define OFF_KL    18432                    // keys lo
#define OFF_WQH   36864                    // Weff^T hi [64][72]     :  9216
#define OFF_WQL   46080
#define OFF_W2H   55296                    // W2^T  hi [32][72]      :  4608
#define OFF_W2L   59904
#define OFF_SC    64512                    // fp32 scalars
#define SMEM_TOTAL (64512 + 1920)          // 66432 B -> 3 CTAs/SM

// ---- device scratch (written by prep kernel, read by main) ----
__device__ __align__(128) uint32_t gWqH[(size_t)MAXB * 2048];  // [b][j][i-pair] 32 MB
__device__ __align__(128) uint32_t gWqL[(size_t)MAXB * 2048];  // 32 MB
__device__ __align__(128) uint32_t gW2H[1024];                 // [n][i-pair]
__device__ __align__(128) uint32_t gW2L[1024];
__device__ float gQWb[(size_t)MAXB * 64];

// ---------------- PTX helpers (baseline, no sm_103a-only features) ----------------
static __device__ __forceinline__ uint32_t smem_u32(const void* p) {
    uint32_t a;
    asm("{ .reg .u64 t; cvta.to.shared.u64 t, %1; cvt.u32.u64 %0, t; }" : "=r"(a) : "l"(p));
    return a;
}

#define LDMX4(r, addr) \
    asm volatile("ldmatrix.sync.aligned.m8n8.x4.shared.b16 {%0,%1,%2,%3}, [%4];" \
        : "=r"((r)[0]), "=r"((r)[1]), "=r"((r)[2]), "=r"((r)[3]) : "r"(addr))

#define MMA16816(d, a, b0, b1) \
    asm volatile("mma.sync.aligned.m16n8k16.row.col.f32.bf16.bf16.f32 " \
        "{%0,%1,%2,%3},{%4,%5,%6,%7},{%8,%9},{%0,%1,%2,%3};" \
        : "+f"((d)[0]), "+f"((d)[1]), "+f"((d)[2]), "+f"((d)[3]) \
        : "r"((a)[0]), "r"((a)[1]), "r"((a)[2]), "r"((a)[3]), \
          "r"(b0), "r"(b1))

#define CP_ASYNC16(dst, src) \
    asm volatile("cp.async.cg.shared.global [%0], [%1], 16;" :: "r"(dst), "l"(src))

// split (x0 -> low half, x1 -> high half) into hi bf16x2 + residual-lo bf16x2
static __device__ __forceinline__ uint2 split2(float x0, float x1) {
    uint32_t h;
    asm("cvt.rn.bf16x2.f32 %0, %1, %2;" : "=r"(h) : "f"(x1), "f"(x0));
    const float f0 = __uint_as_float(h << 16);
    const float f1 = __uint_as_float(h & 0xffff0000u);
    uint32_t l;
    asm("cvt.rn.bf16x2.f32 %0, %1, %2;" : "=r"(l) : "f"(x1 - f1), "f"(x0 - f0));
    return make_uint2(h, l);
}

__device__ __forceinline__ float warpRedMax(float v) {
    #pragma unroll
    for (int o = 16; o > 0; o >>= 1) v = fmaxf(v, __shfl_xor_sync(0xffffffffu, v, o));
    return v;
}
__device__ __forceinline__ float warpRedSum(float v) {
    #pragma unroll
    for (int o = 16; o > 0; o >>= 1) v += __shfl_xor_sync(0xffffffffu, v, o);
    return v;
}

// ================== prep kernel: per-batch weight transform ==================
#define PREP_BATCHES 8
#define PREP_SMEM ((3 * 4096 + 64 + 256) * 4)

extern "C" __global__ void __launch_bounds__(256)
prep_kernel(const float* __restrict__ query,
            const float* __restrict__ W1,
            const float* __restrict__ b1,
            const float* __restrict__ W2,
            int B)
{
    extern __shared__ float psm[];
    float* BC  = psm;            // (W1b - W1c)[i][j]
    float* DD  = BC + 4096;      // W1d[i][j]
    float* AC  = DD + 4096;      // (W1a + W1c)[i][j]
    float* qv  = AC + 4096;      // 64
    float* red = qv + 64;        // 256
    const int tid = threadIdx.x;

    // batch-independent W2 strip image (CTA 0 only)
    if (blockIdx.x == 0) {
        for (int idx = tid; idx < 1024; idx += 256) {
            const int n = idx >> 5, ip = idx & 31, i0 = ip * 2;
            const uint2 p = split2(W2[i0 * 32 + n], W2[(i0 + 1) * 32 + n]);
            gW2H[idx] = p.x;
            gW2L[idx] = p.y;
        }
    }

    // stage combined W1 planes
    for (int idx = tid; idx < 4096; idx += 256) {
        const float a = W1[idx], bb = W1[4096 + idx],
                    c = W1[8192 + idx], d = W1[12288 + idx];
        BC[idx] = bb - c;
        DD[idx] = d;
        AC[idx] = a + c;
    }
    __syncthreads();

    #pragma unroll 1
    for (int bb = 0; bb < PREP_BATCHES; bb++) {
        const int batch = blockIdx.x * PREP_BATCHES + bb;
        if (batch >= B || batch >= MAXB) break;
        if (tid < 64) qv[tid] = query[(size_t)batch * 64 + tid];
        __syncthreads();

        // Weff^T rows [j][i] (i-pairs): gWq*[batch][j*32 + ip]
        for (int idx = tid; idx < 2048; idx += 256) {
            const int j = idx >> 5, ip = idx & 31, i0 = ip * 2;
            const float w0 = BC[i0 * 64 + j]       + qv[i0]     * DD[i0 * 64 + j];
            const float w1 = BC[(i0 + 1) * 64 + j] + qv[i0 + 1] * DD[(i0 + 1) * 64 + j];
            const uint2 p = split2(w0, w1);
            gWqH[(size_t)batch * 2048 + idx] = p.x;
            gWqL[(size_t)batch * 2048 + idx] = p.y;
        }
        // qWb partials
        {
            const int j = tid & 63, g = tid >> 6;
            float s = 0.f;
            #pragma unroll 4
            for (int i = 16 * g; i < 16 * g + 16; i++)
                s += qv[i] * AC[i * 64 + j];
            red[tid] = s;
        }
        __syncthreads();
        if (tid < 64)
            gQWb[(size_t)batch * 64 + tid] =
                b1[tid] + red[tid] + red[64 + tid] + red[128 + tid] + red[192 + tid];
        __syncthreads();
    }
}

// ================== main kernel ==================
extern "C" __global__ void __launch_bounds__(NTHREADS, 3)
asp_kernel(const float* __restrict__ keys,
           const int*   __restrict__ klw,
           const float* __restrict__ W3,
           const float* __restrict__ b2,
           const float* __restrict__ b3,
           float* __restrict__ out)
{
    extern __shared__ char sbase[];
    const uint32_t sb = smem_u32(sbase);

    float* qWbS = (float*)(sbase + OFF_SC);          // 64
    float* b2S  = qWbS + 64;                         // 32
    float* W3S  = b2S  + 32;                         // 32
    float* wS   = W3S  + 32;                         // 256
    float* redS = wS   + 256;                        // 32

    const int b    = blockIdx.x;
    const int tid  = threadIdx.x;
    const int lane = tid & 31;
    const int warp = tid >> 5;

    const float* kg = keys + (size_t)b * T_REAL * 64;

    int len;
    {
        const bool is64 = ((klw[1] | klw[3] | klw[5] | klw[7] | klw[9] | klw[11]) == 0);
        len = is64 ? klw[2 * b] : klw[b];
    }
    const float b3v = b3[0];

    // ---- prologue: cp.async weight strips from prep scratch ----
    {
        const char* srcH = (const char*)gWqH + (size_t)b * 8192;
        const char* srcL = (const char*)gWqL + (size_t)b * 8192;
        #pragma unroll
        for (int k = 0; k < 2; k++) {
            const int c = tid + k * 256;
            const uint32_t off = (uint32_t)(c >> 3) * ROWB + (c & 7) * 16;
            CP_ASYNC16(sb + OFF_WQH + off, srcH + c * 16);
            CP_ASYNC16(sb + OFF_WQL + off, srcL + c * 16);
        }
        {   // W2: 256 chunks
            const int c = tid;
            const uint32_t off = (uint32_t)(c >> 3) * ROWB + (c & 7) * 16;
            CP_ASYNC16(sb + OFF_W2H + off, (const char*)gW2H + c * 16);
            CP_ASYNC16(sb + OFF_W2L + off, (const char*)gW2L + c * 16);
        }
        asm volatile("cp.async.commit_group;");
    }
    if (tid < 64)       qWbS[tid]   = gQWb[(size_t)b * 64 + tid];
    else if (tid < 96)  W3S[tid-64] = W3[tid-64];
    else if (tid < 128) b2S[tid-96] = b2[tid-96];
    asm volatile("cp.async.wait_group 0;");
    __syncthreads();

    // ---- ldmatrix lane addressing ----
    const uint32_t laneR16 = lane & 15;
    const uint32_t laneC   = (lane >> 4) << 3;
    const uint32_t bNt = (lane >> 4) & 1;
    const uint32_t bK  = ((lane >> 3) & 1) << 3;
    const uint32_t bR  = lane & 7;
    const uint32_t bBase = (uint32_t)(bNt * 8 + bR) * ROWB + bK * 2;

    // per-warp keys strips
    const uint32_t myKH = sb + OFF_KH + warp * WSTRIP;
    const uint32_t myKL = sb + OFF_KL + warp * WSTRIP;
    char* myKHp = sbase + OFF_KH + warp * WSTRIP;
    char* myKLp = sbase + OFF_KL + warp * WSTRIP;

    // ================= per-warp independent 16-row blocks =================
    #pragma unroll 1
    for (int bi = 0; bi < 2; bi++) {
        const int blk = warp + bi * 8;
        if (blk * 16 >= T_REAL) break;          // blocks 13..15: fully masked

        // ---- stage this warp's 16 keys rows hi/lo (zero-pad t >= 200) ----
        __syncwarp();
        #pragma unroll
        for (int it = 0; it < 8; it++) {
            const int idx = it * 32 + lane;
            const int row = idx >> 4, q4 = idx & 15;
            const int t = blk * 16 + row;
            float4 v = make_float4(0.f, 0.f, 0.f, 0.f);
            if (t < T_REAL) v = ((const float4*)kg)[t * 16 + q4];
            const uint2 p01 = split2(v.x, v.y);
            const uint2 p23 = split2(v.z, v.w);
            *(uint2*)(myKHp + row*ROWB + q4*8) = make_uint2(p01.x, p23.x);
            *(uint2*)(myKLp + row*ROWB + q4*8) = make_uint2(p01.y, p23.y);
        }
        __syncwarp();

        uint32_t a2h[4][4], a2l[4][4];

        // layer 1 in two nt-halves (keeps c1 live-range at 16 regs)
        #pragma unroll
        for (int hf = 0; hf < 2; hf++) {
            float c1[4][4];
            #pragma unroll
            for (int q = 0; q < 4; q++)
                #pragma unroll
                for (int x = 0; x < 4; x++) c1[q][x] = 0.f;

            #pragma unroll
            for (int kk = 0; kk < 4; kk++) {
                const uint32_t aoff = laneR16 * ROWB + (kk*16 + laneC) * 2;
                uint32_t aH[4], aL[4];
                LDMX4(aH, myKH + aoff);
                LDMX4(aL, myKL + aoff);
                #pragma unroll
                for (int pp = 0; pp < 2; pp++) {
                    const int ntp = hf * 2 + pp;
                    const uint32_t boff = (uint32_t)(ntp * 16) * ROWB + kk * 32 + bBase;
                    uint32_t bH[4], bL[4];
                    LDMX4(bH, sb + OFF_WQH + boff);
                    LDMX4(bL, sb + OFF_WQL + boff);
                    MMA16816(c1[pp*2+0], aH, bH[0], bH[1]);
                    MMA16816(c1[pp*2+0], aH, bL[0], bL[1]);
                    MMA16816(c1[pp*2+0], aL, bH[0], bH[1]);
                    MMA16816(c1[pp*2+1], aH, bH[2], bH[3]);
                    MMA16816(c1[pp*2+1], aH, bL[2], bL[3]);
                    MMA16816(c1[pp*2+1], aL, bH[2], bH[3]);
                }
            }
            // epilogue 1: relu(C1 + qWb) -> split -> layer-2 A frags (in regs)
            #pragma unroll
            for (int q = 0; q < 4; q++) {
                const int nt = hf * 4 + q;
                const int n0 = nt*8 + 2*(lane & 3);
                const float x0 = fmaxf(c1[q][0] + qWbS[n0],   0.f);
                const float x1 = fmaxf(c1[q][1] + qWbS[n0+1], 0.f);
                const float x2 = fmaxf(c1[q][2] + qWbS[n0],   0.f);
                const float x3 = fmaxf(c1[q][3] + qWbS[n0+1], 0.f);
                const uint2 p01 = split2(x0, x1);
                const uint2 p23 = split2(x2, x3);
                const int kk2 = nt >> 1, s = (nt & 1) * 2;
                a2h[kk2][s+0] = p01.x;  a2h[kk2][s+1] = p23.x;
                a2l[kk2][s+0] = p01.y;  a2l[kk2][s+1] = p23.y;
            }
        }

        // ---- layer 2: C2[16 x 32] ----
        float c2[4][4];
        #pragma unroll
        for (int q = 0; q < 4; q++)
            #pragma unroll
            for (int x = 0; x < 4; x++) c2[q][x] = 0.f;

        #pragma unroll
        for (int kk = 0; kk < 4; kk++) {
            #pragma unroll
            for (int pp = 0; pp < 2; pp++) {
                const uint32_t boff = (uint32_t)(pp * 16) * ROWB + kk * 32 + bBase;
                uint32_t bH[4], bL[4];
                LDMX4(bH, sb + OFF_W2H + boff);
                LDMX4(bL, sb + OFF_W2L + boff);
                MMA16816(c2[pp*2+0], a2h[kk], bH[0], bH[1]);
                MMA16816(c2[pp*2+0], a2h[kk], bL[0], bL[1]);
                MMA16816(c2[pp*2+0], a2l[kk], bH[0], bH[1]);
                MMA16816(c2[pp*2+1], a2h[kk], bH[2], bH[3]);
                MMA16816(c2[pp*2+1], a2h[kk], bL[2], bL[3]);
                MMA16816(c2[pp*2+1], a2l[kk], bH[2], bH[3]);
            }
        }

        // ---- epilogue 2: score = relu(C2 + b2) . W3 (quad reduce) ----
        float p0 = 0.f, p1 = 0.f;
        #pragma unroll
        for (int nt = 0; nt < 4; nt++) {
            const int n0 = nt*8 + 2*(lane & 3);
            const float w0 = W3S[n0], w1 = W3S[n0+1];
            const float bb0 = b2S[n0], bb1 = b2S[n0+1];
            p0 += fmaxf(c2[nt][0] + bb0, 0.f) * w0 + fmaxf(c2[nt][1] + bb1, 0.f) * w1;
            p1 += fmaxf(c2[nt][2] + bb0, 0.f) * w0 + fmaxf(c2[nt][3] + bb1, 0.f) * w1;
        }
        p0 += __shfl_xor_sync(0xffffffffu, p0, 1);
        p0 += __shfl_xor_sync(0xffffffffu, p0, 2);
        p1 += __shfl_xor_sync(0xffffffffu, p1, 1);
        p1 += __shfl_xor_sync(0xffffffffu, p1, 2);
        if ((lane & 3) == 0) {
            wS[blk*16 + (lane >> 2)]     = p0 + b3v;
            wS[blk*16 + (lane >> 2) + 8] = p1 + b3v;
        }
    }
    __syncthreads();

    // ---- mask + softmax over wS ----
    float sc;
    if (tid < T_REAL) sc = (tid < len) ? wS[tid] : MASK_VAL_F;
    else              sc = -FLT_MAX;

    float m = warpRedMax(sc);
    if ((tid & 31) == 0) redS[tid >> 5] = m;
    __syncthreads();
    float bm = redS[0];
    #pragma unroll
    for (int w = 1; w < 8; w++) bm = fmaxf(bm, redS[w]);
    __syncthreads();
    const float e = (tid < T_REAL) ? expf(sc - bm) : 0.f;
    float s1 = warpRedSum(e);
    if ((tid & 31) == 0) redS[tid >> 5] = s1;
    __syncthreads();
    float bs = 0.f;
    #pragma unroll
    for (int w = 0; w < 8; w++) bs += redS[w];
    wS[tid] = e * (1.0f / bs);
    __syncthreads();

    // ---- weighted sum: out[e] = sum_t w_t * keys[t][e] (fp32 keys via L2) ----
    float* scr = (float*)(sbase + OFF_WQH);   // reuse as fp32 scratch (256 floats)
    {
        const int e_ = tid & 63;
        const int g  = tid >> 6;
        float acc0 = 0.f, acc1 = 0.f;
        #pragma unroll 4
        for (int t = g; t < 192; t += 8) {
            acc0 += wS[t]     * kg[t * 64 + e_];
            acc1 += wS[t + 4] * kg[(t + 4) * 64 + e_];
        }
        acc0 += wS[192 + g] * kg[(192 + g) * 64 + e_];
        acc1 += wS[196 + g] * kg[(196 + g) * 64 + e_];
        scr[g * 64 + e_] = acc0 + acc1;
    }
    __syncthreads();
    if (tid < 64)
        out[(size_t)b * 64 + tid] =
            scr[tid] + scr[64 + tid] + scr[128 + tid] + scr[192 + tid];
}

extern "C" void kernel_launch(void* const* d_in, const int* in_sizes, int n_in,
                              void* d_out, int out_size) {
    const float* query = (const float*)d_in[0];
    const float* keys  = (const float*)d_in[1];
    const int*   klen  = (const int*)  d_in[2];
    const float* W1    = (const float*)d_in[3];
    const float* b1    = (const float*)d_in[4];
    const float* W2    = (const float*)d_in[5];
    const float* b2    = (const float*)d_in[6];
    const float* W3    = (const float*)d_in[7];
    const float* b3    = (const float*)d_in[8];
    float* out = (float*)d_out;

    const int B = in_sizes[0] / 64;

    cudaFuncSetAttribute(prep_kernel,
                         cudaFuncAttributeMaxDynamicSharedMemorySize, PREP_SMEM);
    cudaFuncSetAttribute(asp_kernel,
                         cudaFuncAttributeMaxDynamicSharedMemorySize, SMEM_TOTAL);

    const int prepGrid = (B + PREP_BATCHES - 1) / PREP_BATCHES;
    prep_kernel<<<prepGrid, 256, PREP_SMEM>>>(query, W1, b1, W2, B);
    asp_kernel<<<B, NTHREADS, SMEM_TOTAL>>>(keys, klen, W3, b2, b3, out);
}

// round 11
// speedup vs baseline: 2.6456x; 2.6456x over previous
#include <cuda_runtime.h>
#include <cuda_fp16.h>
#include <stdint.h>
#include <math.h>
#include <float.h>

#define NTHREADS   256
#define T_REAL     200
#define MASK_VAL_F (-4294967296.0f)   // jnp.float32(-2**32+1) rounds to -2^32

// fp16 SMEM tiles, row stride 72 elements (144 B: 16B-aligned, conflict-free ldmatrix)
#define ROWB       144
#define WSTRIP     (16 * ROWB)             // 2304 B per-warp keys strip

// ---- SMEM byte offsets ----
#define OFF_K     0                        // keys fp16, 8 warp-strips : 18432
#define OFF_WQ    18432                    // Weff^T fp16 [64][72]     :  9216
#define OFF_W2    27648                    // W2^T  fp16 [32][72]      :  4608
#define OFF_SC    32256                    // fp32 scalars
#define SMEM_TOTAL (32256 + 1920)          // 34176 B -> 4+ CTAs/SM

// ---------------- PTX helpers (baseline, no sm_103a-only features) ----------------
static __device__ __forceinline__ uint32_t smem_u32(const void* p) {
    uint32_t a;
    asm("{ .reg .u64 t; cvta.to.shared.u64 t, %1; cvt.u32.u64 %0, t; }" : "=r"(a) : "l"(p));
    return a;
}

#define LDMX4(r, addr) \
    asm volatile("ldmatrix.sync.aligned.m8n8.x4.shared.b16 {%0,%1,%2,%3}, [%4];" \
        : "=r"((r)[0]), "=r"((r)[1]), "=r"((r)[2]), "=r"((r)[3]) : "r"(addr))

#define MMA16816(d, a0, a1, a2, a3, b0, b1) \
    asm volatile("mma.sync.aligned.m16n8k16.row.col.f32.f16.f16.f32 " \
        "{%0,%1,%2,%3},{%4,%5,%6,%7},{%8,%9},{%0,%1,%2,%3};" \
        : "+f"((d)[0]), "+f"((d)[1]), "+f"((d)[2]), "+f"((d)[3]) \
        : "r"(a0), "r"(a1), "r"(a2), "r"(a3), "r"(b0), "r"(b1))

// pack (x0 -> low half, x1 -> high half) into one fp16x2 register
static __device__ __forceinline__ uint32_t h2pack(float x0, float x1) {
    uint32_t h;
    asm("cvt.rn.f16x2.f32 %0, %1, %2;" : "=r"(h) : "f"(x1), "f"(x0));
    return h;
}

__device__ __forceinline__ float warpRedMax(float v) {
    #pragma unroll
    for (int o = 16; o > 0; o >>= 1) v = fmaxf(v, __shfl_xor_sync(0xffffffffu, v, o));
    return v;
}
__device__ __forceinline__ float warpRedSum(float v) {
    #pragma unroll
    for (int o = 16; o > 0; o >>= 1) v += __shfl_xor_sync(0xffffffffu, v, o);
    return v;
}

extern "C" __global__ void __launch_bounds__(NTHREADS, 4)
asp_kernel(const float* __restrict__ query,
           const float* __restrict__ keys,
           const int*   __restrict__ klw,
           const float* __restrict__ W1,
           const float* __restrict__ b1,
           const float* __restrict__ W2,
           const float* __restrict__ b2,
           const float* __restrict__ W3,
           const float* __restrict__ b3,
           float* __restrict__ out)
{
    extern __shared__ char sbase[];
    const uint32_t sb = smem_u32(sbase);

    float* qS   = (float*)(sbase + OFF_SC);          // 64
    float* qWbS = qS   + 64;                         // 64
    float* b2S  = qWbS + 64;                         // 32
    float* W3S  = b2S  + 32;                         // 32
    float* wS   = W3S  + 32;                         // 256 (also qWb-partial scratch)
    float* redS = wS   + 256;                        // 32

    const int b    = blockIdx.x;
    const int tid  = threadIdx.x;
    const int lane = tid & 31;
    const int warp = tid >> 5;

    const float* qg = query + (size_t)b * 64;
    const float* kg = keys  + (size_t)b * T_REAL * 64;

    int len;
    {
        const bool is64 = ((klw[1] | klw[3] | klw[5] | klw[7] | klw[9] | klw[11]) == 0);
        len = is64 ? klw[2 * b] : klw[b];
    }
    const float b3v = b3[0];

    // ---- stage small operands ----
    if (tid < 64)       qS[tid]     = qg[tid];
    else if (tid < 96)  W3S[tid-64] = W3[tid-64];
    else if (tid < 128) b2S[tid-96] = b2[tid-96];
    __syncthreads();

    // ---- qWb partials: thread (g=tid>>6, j=tid&63) sums i in [16g,16g+16) ----
    {
        const int j = tid & 63, g = tid >> 6;
        float s = 0.f;
        #pragma unroll 4
        for (int i = 16 * g; i < 16 * g + 16; i++)
            s += qS[i] * (W1[i*64 + j] + W1[(128+i)*64 + j]);
        wS[tid] = s;
    }
    // ---- Weff^T fp16 (paired over i): WqT[j][i] ----
    for (int idx = tid; idx < 2048; idx += NTHREADS) {
        const int j = idx & 63, i0 = (idx >> 6) * 2;
        const float w0 = W1[(64+i0)*64 + j] - W1[(128+i0)*64 + j] + qS[i0]   * W1[(192+i0)*64 + j];
        const float w1 = W1[(65+i0)*64 + j] - W1[(129+i0)*64 + j] + qS[i0+1] * W1[(193+i0)*64 + j];
        *(uint32_t*)(sbase + OFF_WQ + j*ROWB + i0*2) = h2pack(w0, w1);
    }
    // ---- W2^T fp16: W2T[n][i] ----
    for (int idx = tid; idx < 1024; idx += NTHREADS) {
        const int n = idx & 31, i0 = (idx >> 5) * 2;
        *(uint32_t*)(sbase + OFF_W2 + n*ROWB + i0*2) =
            h2pack(W2[i0*32 + n], W2[(i0+1)*32 + n]);
    }
    __syncthreads();
    if (tid < 64)
        qWbS[tid] = b1[tid] + wS[tid] + wS[64+tid] + wS[128+tid] + wS[192+tid];
    __syncthreads();   // qWbS ready; wS free for score writes

    // ---- ldmatrix lane addressing ----
    const uint32_t laneR16 = lane & 15;
    const uint32_t laneC   = (lane >> 4) << 3;
    // B (x4, paired nt)
    const uint32_t bNt = (lane >> 4) & 1;
    const uint32_t bK  = ((lane >> 3) & 1) << 3;
    const uint32_t bR  = lane & 7;
    const uint32_t bBase = (uint32_t)(bNt * 8 + bR) * ROWB + bK * 2;

    // per-warp keys strip
    const uint32_t myK  = sb + OFF_K + warp * WSTRIP;
    char* myKp = sbase + OFF_K + warp * WSTRIP;

    // ================= per-warp independent 16-row blocks =================
    // warp w handles blocks {w, w+8}; blocks with all rows >= 200 skipped.
    #pragma unroll 1
    for (int bi = 0; bi < 2; bi++) {
        const int blk = warp + bi * 8;
        if (blk * 16 >= T_REAL) break;          // blocks 13..15: fully masked

        // ---- stage this warp's 16 keys rows fp16 (zero-pad t >= 200) ----
        __syncwarp();
        #pragma unroll
        for (int it = 0; it < 8; it++) {
            const int idx = it * 32 + lane;
            const int row = idx >> 4, q4 = idx & 15;
            const int t = blk * 16 + row;
            float4 v = make_float4(0.f, 0.f, 0.f, 0.f);
            if (t < T_REAL) v = ((const float4*)kg)[t * 16 + q4];
            *(uint2*)(myKp + row*ROWB + q4*8) =
                make_uint2(h2pack(v.x, v.y), h2pack(v.z, v.w));
        }
        __syncwarp();

        // ---- layer 1: C1[16 x 64] ----
        float c1[8][4];
        #pragma unroll
        for (int q = 0; q < 8; q++)
            #pragma unroll
            for (int x = 0; x < 4; x++) c1[q][x] = 0.f;

        #pragma unroll
        for (int kk = 0; kk < 4; kk++) {
            const uint32_t aoff = laneR16 * ROWB + (kk*16 + laneC) * 2;
            uint32_t aH[4];
            LDMX4(aH, myK + aoff);
            #pragma unroll
            for (int pp = 0; pp < 4; pp++) {           // nt pairs
                const uint32_t boff = (uint32_t)(pp * 16) * ROWB + kk * 32 + bBase;
                uint32_t bH[4];
                LDMX4(bH, sb + OFF_WQ + boff);
                MMA16816(c1[pp*2+0], aH[0], aH[1], aH[2], aH[3], bH[0], bH[1]);
                MMA16816(c1[pp*2+1], aH[0], aH[1], aH[2], aH[3], bH[2], bH[3]);
            }
        }

        // ---- epilogue 1: h1 = relu(C1 + qWb) -> fp16 -> layer-2 A frags ----
        uint32_t a2[4][4];
        #pragma unroll
        for (int nt = 0; nt < 8; nt++) {
            const int n0 = nt*8 + 2*(lane & 3);
            const float x0 = fmaxf(c1[nt][0] + qWbS[n0],   0.f);
            const float x1 = fmaxf(c1[nt][1] + qWbS[n0+1], 0.f);
            const float x2 = fmaxf(c1[nt][2] + qWbS[n0],   0.f);
            const float x3 = fmaxf(c1[nt][3] + qWbS[n0+1], 0.f);
            const int kk2 = nt >> 1, s = (nt & 1) * 2;
            a2[kk2][s+0] = h2pack(x0, x1);
            a2[kk2][s+1] = h2pack(x2, x3);
        }

        // ---- layer 2: C2[16 x 32] ----
        float c2[4][4];
        #pragma unroll
        for (int q = 0; q < 4; q++)
            #pragma unroll
            for (int x = 0; x < 4; x++) c2[q][x] = 0.f;

        #pragma unroll
        for (int kk = 0; kk < 4; kk++) {
            #pragma unroll
            for (int pp = 0; pp < 2; pp++) {           // nt pairs (N=32)
                const uint32_t boff = (uint32_t)(pp * 16) * ROWB + kk * 32 + bBase;
                uint32_t bH[4];
                LDMX4(bH, sb + OFF_W2 + boff);
                MMA16816(c2[pp*2+0], a2[kk][0], a2[kk][1], a2[kk][2], a2[kk][3], bH[0], bH[1]);
                MMA16816(c2[pp*2+1], a2[kk][0], a2[kk][1], a2[kk][2], a2[kk][3], bH[2], bH[3]);
            }
        }

        // ---- epilogue 2: score = relu(C2 + b2) . W3 (quad reduce) ----
        float p0 = 0.f, p1 = 0.f;
        #pragma unroll
        for (int nt = 0; nt < 4; nt++) {
            const int n0 = nt*8 + 2*(lane & 3);
            const float w0 = W3S[n0], w1 = W3S[n0+1];
            const float bb0 = b2S[n0], bb1 = b2S[n0+1];
            p0 += fmaxf(c2[nt][0] + bb0, 0.f) * w0 + fmaxf(c2[nt][1] + bb1, 0.f) * w1;
            p1 += fmaxf(c2[nt][2] + bb0, 0.f) * w0 + fmaxf(c2[nt][3] + bb1, 0.f) * w1;
        }
        p0 += __shfl_xor_sync(0xffffffffu, p0, 1);
        p0 += __shfl_xor_sync(0xffffffffu, p0, 2);
        p1 += __shfl_xor_sync(0xffffffffu, p1, 1);
        p1 += __shfl_xor_sync(0xffffffffu, p1, 2);
        if ((lane & 3) == 0) {
            wS[blk*16 + (lane >> 2)]     = p0 + b3v;
            wS[blk*16 + (lane >> 2) + 8] = p1 + b3v;
        }
    }
    __syncthreads();

    // ---- mask + softmax over wS ----
    float sc;
    if (tid < T_REAL) sc = (tid < len) ? wS[tid] : MASK_VAL_F;
    else              sc = -FLT_MAX;

    float m = warpRedMax(sc);
    if ((tid & 31) == 0) redS[tid >> 5] = m;
    __syncthreads();
    float bm = redS[0];
    #pragma unroll
    for (int w = 1; w < 8; w++) bm = fmaxf(bm, redS[w]);
    __syncthreads();
    const float e = (tid < T_REAL) ? expf(sc - bm) : 0.f;
    float s1 = warpRedSum(e);
    if ((tid & 31) == 0) redS[tid >> 5] = s1;
    __syncthreads();
    float bs = 0.f;
    #pragma unroll
    for (int w = 0; w < 8; w++) bs += redS[w];
    wS[tid] = e * (1.0f / bs);
    __syncthreads();

    // ---- weighted sum: out[e] = sum_t w_t * keys[t][e] (fp32 keys via L2) ----
    float* scr = (float*)(sbase + OFF_WQ);   // reuse as fp32 scratch (256 floats)
    {
        const int e_ = tid & 63;
        const int g  = tid >> 6;
        float acc0 = 0.f, acc1 = 0.f;
        #pragma unroll 4
        for (int t = g; t < 192; t += 8) {
            acc0 += wS[t]     * kg[t * 64 + e_];
            acc1 += wS[t + 4] * kg[(t + 4) * 64 + e_];
        }
        acc0 += wS[192 + g] * kg[(192 + g) * 64 + e_];
        acc1 += wS[196 + g] * kg[(196 + g) * 64 + e_];
        scr[g * 64 + e_] = acc0 + acc1;
    }
    __syncthreads();
    if (tid < 64)
        out[(size_t)b * 64 + tid] =
            scr[tid] + scr[64 + tid] + scr[128 + tid] + scr[192 + tid];
}

extern "C" void kernel_launch(void* const* d_in, const int* in_sizes, int n_in,
                              void* d_out, int out_size) {
    const float* query = (const float*)d_in[0];
    const float* keys  = (const float*)d_in[1];
    const int*   klen  = (const int*)  d_in[2];
    const float* W1    = (const float*)d_in[3];
    const float* b1    = (const float*)d_in[4];
    const float* W2    = (const float*)d_in[5];
    const float* b2    = (const float*)d_in[6];
    const float* W3    = (const float*)d_in[7];
    const float* b3    = (const float*)d_in[8];
    float* out = (float*)d_out;

    const int B = in_sizes[0] / 64;

    cudaFuncSetAttribute(asp_kernel,
                         cudaFuncAttributeMaxDynamicSharedMemorySize,
                         SMEM_TOTAL);

    asp_kernel<<<B, NTHREADS, SMEM_TOTAL>>>(query, keys, klen,
                                            W1, b1, W2, b2, W3, b3, out);
}

// round 12
// speedup vs baseline: 2.8225x; 1.0669x over previous
#include <cuda_runtime.h>
#include <cuda_fp16.h>
#include <stdint.h>
#include <math.h>
#include <float.h>

#define NTHREADS   256
#define T_REAL     200
#define MASK_VAL_F (-4294967296.0f)   // jnp.float32(-2**32+1) rounds to -2^32

// fp16 SMEM tiles, row stride 72 elements (144 B: 16B-aligned, conflict-free ldmatrix)
#define ROWB       144
#define WSTRIP     (16 * ROWB)             // 2304 B per 16-row block strip
#define NSTRIPS    13                      // ceil(200/16)

// ---- SMEM byte offsets ----
#define OFF_K     0                        // keys fp16, 13 block strips : 29952
#define OFF_WQ    (NSTRIPS * WSTRIP)       // Weff^T fp16 [64][72] : 9216
#define OFF_W2    (OFF_WQ + 9216)          // W2^T  fp16 [32][72]  : 4608
#define OFF_SC    (OFF_W2 + 4608)          // fp32 scalars
#define SMEM_TOTAL (OFF_SC + 1920)         // 45696 B -> 4 CTAs/SM

// ---------------- PTX helpers (baseline, no sm_103a-only features) ----------------
static __device__ __forceinline__ uint32_t smem_u32(const void* p) {
    uint32_t a;
    asm("{ .reg .u64 t; cvta.to.shared.u64 t, %1; cvt.u32.u64 %0, t; }" : "=r"(a) : "l"(p));
    return a;
}

#define LDMX4(r, addr) \
    asm volatile("ldmatrix.sync.aligned.m8n8.x4.shared.b16 {%0,%1,%2,%3}, [%4];" \
        : "=r"((r)[0]), "=r"((r)[1]), "=r"((r)[2]), "=r"((r)[3]) : "r"(addr))

#define MMA16816(d, a0, a1, a2, a3, b0, b1) \
    asm volatile("mma.sync.aligned.m16n8k16.row.col.f32.f16.f16.f32 " \
        "{%0,%1,%2,%3},{%4,%5,%6,%7},{%8,%9},{%0,%1,%2,%3};" \
        : "+f"((d)[0]), "+f"((d)[1]), "+f"((d)[2]), "+f"((d)[3]) \
        : "r"(a0), "r"(a1), "r"(a2), "r"(a3), "r"(b0), "r"(b1))

// pack (x0 -> low half, x1 -> high half) into one fp16x2 register
static __device__ __forceinline__ uint32_t h2pack(float x0, float x1) {
    uint32_t h;
    asm("cvt.rn.f16x2.f32 %0, %1, %2;" : "=r"(h) : "f"(x1), "f"(x0));
    return h;
}

__device__ __forceinline__ float warpRedMax(float v) {
    #pragma unroll
    for (int o = 16; o > 0; o >>= 1) v = fmaxf(v, __shfl_xor_sync(0xffffffffu, v, o));
    return v;
}
__device__ __forceinline__ float warpRedSum(float v) {
    #pragma unroll
    for (int o = 16; o > 0; o >>= 1) v += __shfl_xor_sync(0xffffffffu, v, o);
    return v;
}

extern "C" __global__ void __launch_bounds__(NTHREADS, 4)
asp_kernel(const float* __restrict__ query,
           const float* __restrict__ keys,
           const int*   __restrict__ klw,
           const float* __restrict__ W1,
           const float* __restrict__ b1,
           const float* __restrict__ W2,
           const float* __restrict__ b2,
           const float* __restrict__ W3,
           const float* __restrict__ b3,
           float* __restrict__ out)
{
    extern __shared__ char sbase[];
    const uint32_t sb = smem_u32(sbase);

    float* qS   = (float*)(sbase + OFF_SC);          // 64
    float* qWbS = qS   + 64;                         // 64
    float* b2S  = qWbS + 64;                         // 32
    float* W3S  = b2S  + 32;                         // 32
    float* wS   = W3S  + 32;                         // 256 (also qWb-partial scratch)
    float* redS = wS   + 256;                        // 32

    const int b    = blockIdx.x;
    const int tid  = threadIdx.x;
    const int lane = tid & 31;
    const int warp = tid >> 5;

    const float* qg = query + (size_t)b * 64;
    const float* kg = keys  + (size_t)b * T_REAL * 64;

    int len;
    {
        const bool is64 = ((klw[1] | klw[3] | klw[5] | klw[7] | klw[9] | klw[11]) == 0);
        len = is64 ? klw[2 * b] : klw[b];
    }
    const float b3v = b3[0];

    // ---- stage small operands ----
    if (tid < 64)       qS[tid]     = qg[tid];
    else if (tid < 96)  W3S[tid-64] = W3[tid-64];
    else if (tid < 128) b2S[tid-96] = b2[tid-96];
    __syncthreads();

    // ---- qWb partials: thread (g=tid>>6, j=tid&63) sums i in [16g,16g+16) ----
    {
        const int j = tid & 63, g = tid >> 6;
        float s = 0.f;
        #pragma unroll 4
        for (int i = 16 * g; i < 16 * g + 16; i++)
            s += qS[i] * (W1[i*64 + j] + W1[(128+i)*64 + j]);
        wS[tid] = s;
    }
    // ---- Weff^T fp16 (paired over i): WqT[j][i] ----
    for (int idx = tid; idx < 2048; idx += NTHREADS) {
        const int j = idx & 63, i0 = (idx >> 6) * 2;
        const float w0 = W1[(64+i0)*64 + j] - W1[(128+i0)*64 + j] + qS[i0]   * W1[(192+i0)*64 + j];
        const float w1 = W1[(65+i0)*64 + j] - W1[(129+i0)*64 + j] + qS[i0+1] * W1[(193+i0)*64 + j];
        *(uint32_t*)(sbase + OFF_WQ + j*ROWB + i0*2) = h2pack(w0, w1);
    }
    // ---- W2^T fp16: W2T[n][i] ----
    for (int idx = tid; idx < 1024; idx += NTHREADS) {
        const int n = idx & 31, i0 = (idx >> 5) * 2;
        *(uint32_t*)(sbase + OFF_W2 + n*ROWB + i0*2) =
            h2pack(W2[i0*32 + n], W2[(i0+1)*32 + n]);
    }
    __syncthreads();
    if (tid < 64)
        qWbS[tid] = b1[tid] + wS[tid] + wS[64+tid] + wS[128+tid] + wS[192+tid];
    __syncthreads();   // qWbS ready; wS free for score writes

    // ---- ldmatrix lane addressing ----
    const uint32_t laneR16 = lane & 15;
    const uint32_t laneC   = (lane >> 4) << 3;
    // B (x4, paired nt)
    const uint32_t bNt = (lane >> 4) & 1;
    const uint32_t bK  = ((lane >> 3) & 1) << 3;
    const uint32_t bR  = lane & 7;
    const uint32_t bBase = (uint32_t)(bNt * 8 + bR) * ROWB + bK * 2;

    // ---- stage BOTH assigned key blocks into dedicated strips (no reuse) ----
    #pragma unroll 1
    for (int bi = 0; bi < 2; bi++) {
        const int blk = warp + bi * 8;
        if (blk * 16 >= T_REAL) break;          // blocks 13..15 don't exist
        char* stp = sbase + OFF_K + blk * WSTRIP;
        #pragma unroll
        for (int it = 0; it < 8; it++) {
            const int idx = it * 32 + lane;
            const int row = idx >> 4, q4 = idx & 15;
            const int t = blk * 16 + row;
            float4 v = make_float4(0.f, 0.f, 0.f, 0.f);
            if (t < T_REAL) v = ((const float4*)kg)[t * 16 + q4];
            *(uint2*)(stp + row*ROWB + q4*8) =
                make_uint2(h2pack(v.x, v.y), h2pack(v.z, v.w));
        }
    }
    __syncwarp();

    // ================= per-warp independent 16-row blocks =================
    #pragma unroll 1
    for (int bi = 0; bi < 2; bi++) {
        const int blk = warp + bi * 8;
        if (blk * 16 >= T_REAL) break;
        const uint32_t myK = sb + OFF_K + blk * WSTRIP;

        // ---- layer 1: C1[16 x 64] ----
        float c1[8][4];
        #pragma unroll
        for (int q = 0; q < 8; q++)
            #pragma unroll
            for (int x = 0; x < 4; x++) c1[q][x] = 0.f;

        #pragma unroll
        for (int kk = 0; kk < 4; kk++) {
            const uint32_t aoff = laneR16 * ROWB + (kk*16 + laneC) * 2;
            uint32_t aH[4];
            LDMX4(aH, myK + aoff);
            #pragma unroll
            for (int pp = 0; pp < 4; pp++) {           // nt pairs
                const uint32_t boff = (uint32_t)(pp * 16) * ROWB + kk * 32 + bBase;
                uint32_t bH[4];
                LDMX4(bH, sb + OFF_WQ + boff);
                MMA16816(c1[pp*2+0], aH[0], aH[1], aH[2], aH[3], bH[0], bH[1]);
                MMA16816(c1[pp*2+1], aH[0], aH[1], aH[2], aH[3], bH[2], bH[3]);
            }
        }

        // ---- epilogue 1: h1 = relu(C1 + qWb) -> fp16 -> layer-2 A frags ----
        uint32_t a2[4][4];
        #pragma unroll
        for (int nt = 0; nt < 8; nt++) {
            const int n0 = nt*8 + 2*(lane & 3);
            const float x0 = fmaxf(c1[nt][0] + qWbS[n0],   0.f);
            const float x1 = fmaxf(c1[nt][1] + qWbS[n0+1], 0.f);
            const float x2 = fmaxf(c1[nt][2] + qWbS[n0],   0.f);
            const float x3 = fmaxf(c1[nt][3] + qWbS[n0+1], 0.f);
            const int kk2 = nt >> 1, s = (nt & 1) * 2;
            a2[kk2][s+0] = h2pack(x0, x1);
            a2[kk2][s+1] = h2pack(x2, x3);
        }

        // ---- layer 2: C2[16 x 32] ----
        float c2[4][4];
        #pragma unroll
        for (int q = 0; q < 4; q++)
            #pragma unroll
            for (int x = 0; x < 4; x++) c2[q][x] = 0.f;

        #pragma unroll
        for (int kk = 0; kk < 4; kk++) {
            #pragma unroll
            for (int pp = 0; pp < 2; pp++) {           // nt pairs (N=32)
                const uint32_t boff = (uint32_t)(pp * 16) * ROWB + kk * 32 + bBase;
                uint32_t bH[4];
                LDMX4(bH, sb + OFF_W2 + boff);
                MMA16816(c2[pp*2+0], a2[kk][0], a2[kk][1], a2[kk][2], a2[kk][3], bH[0], bH[1]);
                MMA16816(c2[pp*2+1], a2[kk][0], a2[kk][1], a2[kk][2], a2[kk][3], bH[2], bH[3]);
            }
        }

        // ---- epilogue 2: score = relu(C2 + b2) . W3 (quad reduce) ----
        float p0 = 0.f, p1 = 0.f;
        #pragma unroll
        for (int nt = 0; nt < 4; nt++) {
            const int n0 = nt*8 + 2*(lane & 3);
            const float w0 = W3S[n0], w1 = W3S[n0+1];
            const float bb0 = b2S[n0], bb1 = b2S[n0+1];
            p0 += fmaxf(c2[nt][0] + bb0, 0.f) * w0 + fmaxf(c2[nt][1] + bb1, 0.f) * w1;
            p1 += fmaxf(c2[nt][2] + bb0, 0.f) * w0 + fmaxf(c2[nt][3] + bb1, 0.f) * w1;
        }
        p0 += __shfl_xor_sync(0xffffffffu, p0, 1);
        p0 += __shfl_xor_sync(0xffffffffu, p0, 2);
        p1 += __shfl_xor_sync(0xffffffffu, p1, 1);
        p1 += __shfl_xor_sync(0xffffffffu, p1, 2);
        if ((lane & 3) == 0) {
            wS[blk*16 + (lane >> 2)]     = p0 + b3v;
            wS[blk*16 + (lane >> 2) + 8] = p1 + b3v;
        }
    }
    __syncthreads();

    // ---- mask + softmax over wS ----
    float sc;
    if (tid < T_REAL) sc = (tid < len) ? wS[tid] : MASK_VAL_F;
    else              sc = -FLT_MAX;

    float m = warpRedMax(sc);
    if ((tid & 31) == 0) redS[tid >> 5] = m;
    __syncthreads();
    float bm = redS[0];
    #pragma unroll
    for (int w = 1; w < 8; w++) bm = fmaxf(bm, redS[w]);
    __syncthreads();
    const float e = (tid < T_REAL) ? expf(sc - bm) : 0.f;
    float s1 = warpRedSum(e);
    if ((tid & 31) == 0) redS[tid >> 5] = s1;
    __syncthreads();
    float bs = 0.f;
    #pragma unroll
    for (int w = 0; w < 8; w++) bs += redS[w];
    wS[tid] = e * (1.0f / bs);
    __syncthreads();

    // ---- weighted sum from SMEM fp16 keys: out[e] = sum_t w_t * k16[t][e] ----
    // strip layout linearizes: addr = OFF_K + t*ROWB + e*2
    float* scr = (float*)(sbase + OFF_WQ);   // reuse as fp32 scratch (256 floats)
    {
        const int e_ = tid & 63;
        const int g  = tid >> 6;
        const char* kbase = sbase + OFF_K + e_ * 2;
        float acc0 = 0.f, acc1 = 0.f;
        #pragma unroll 4
        for (int t = g; t < 192; t += 8) {
            acc0 += wS[t]     * __half2float(*(const __half*)(kbase + t * ROWB));
            acc1 += wS[t + 4] * __half2float(*(const __half*)(kbase + (t + 4) * ROWB));
        }
        acc0 += wS[192 + g] * __half2float(*(const __half*)(kbase + (192 + g) * ROWB));
        acc1 += wS[196 + g] * __half2float(*(const __half*)(kbase + (196 + g) * ROWB));
        scr[g * 64 + e_] = acc0 + acc1;
    }
    __syncthreads();
    if (tid < 64)
        out[(size_t)b * 64 + tid] =
            scr[tid] + scr[64 + tid] + scr[128 + tid] + scr[192 + tid];
}

extern "C" void kernel_launch(void* const* d_in, const int* in_sizes, int n_in,
                              void* d_out, int out_size) {
    const float* query = (const float*)d_in[0];
    const float* keys  = (const float*)d_in[1];
    const int*   klen  = (const int*)  d_in[2];
    const float* W1    = (const float*)d_in[3];
    const float* b1    = (const float*)d_in[4];
    const float* W2    = (const float*)d_in[5];
    const float* b2    = (const float*)d_in[6];
    const float* W3    = (const float*)d_in[7];
    const float* b3    = (const float*)d_in[8];
    float* out = (float*)d_out;

    const int B = in_sizes[0] / 64;

    cudaFuncSetAttribute(asp_kernel,
                         cudaFuncAttributeMaxDynamicSharedMemorySize,
                         SMEM_TOTAL);

    asp_kernel<<<B, NTHREADS, SMEM_TOTAL>>>(query, keys, klen,
                                            W1, b1, W2, b2, W3, b3, out);
}